// round 1
// baseline (speedup 1.0000x reference)
#include <cuda_runtime.h>
#include <cstdint>
#include <cstddef>

// Problem dims (fixed by the dataset)
#define BD 2048   // batch
#define MD 512    // measurements
#define AD 2048   // ambient
#define SD 6144   // S = A*3
#define NB 64     // Cholesky block

// ---------------- device scratch (no allocations allowed) ----------------
__device__ float g_G[AD * AD];        // Gram matrix / Cholesky workspace
__device__ float g_linv[NB * NB];     // inv of diagonal Cholesky block
__device__ float g_dU[AD];            // 1 / u_kk
__device__ float g_x0[BD * AD];       // y @ a
__device__ float g_xh[BD * AD];       // x_hat
__device__ float g_u[BD * SD];        // ADMM u
__device__ float g_w[BD * SD];        // w = z - u
__device__ unsigned g_mm[2];          // [0]=min key, [1]=max key (ordered-uint space)

// ---------------- float <-> order-preserving unsigned ----------------
__device__ __forceinline__ unsigned f2o(float f) {
    unsigned b = __float_as_uint(f);
    return (b & 0x80000000u) ? ~b : (b | 0x80000000u);
}
__device__ __forceinline__ float o2f(unsigned u) {
    unsigned b = (u & 0x80000000u) ? (u ^ 0x80000000u) : ~u;
    return __uint_as_float(b);
}

__global__ void mm_init_k() {
    g_mm[0] = 0xFFFFFFFFu;
    g_mm[1] = 0u;
}

__global__ void mm_reduce_k(const float* __restrict__ x, int n) {
    unsigned mn = 0xFFFFFFFFu, mx = 0u;
    for (int i = blockIdx.x * blockDim.x + threadIdx.x; i < n; i += gridDim.x * blockDim.x) {
        unsigned o = f2o(x[i]);
        mn = min(mn, o);
        mx = max(mx, o);
    }
    __shared__ unsigned smn[256], smx[256];
    smn[threadIdx.x] = mn;
    smx[threadIdx.x] = mx;
    __syncthreads();
    for (int s = 128; s > 0; s >>= 1) {
        if (threadIdx.x < s) {
            smn[threadIdx.x] = min(smn[threadIdx.x], smn[threadIdx.x + s]);
            smx[threadIdx.x] = max(smx[threadIdx.x], smx[threadIdx.x + s]);
        }
        __syncthreads();
    }
    if (threadIdx.x == 0) {
        atomicMin(&g_mm[0], smn[0]);
        atomicMax(&g_mm[1], smx[0]);
    }
}

// ---------------- iteration-1 x_hat = dU * x0 ----------------
__global__ void xhat1_k(const float* __restrict__ x0, const float* __restrict__ dU,
                        float* __restrict__ xh) {
    int i = blockIdx.x * blockDim.x + threadIdx.x;
    xh[i] = dU[i & (AD - 1)] * x0[i];
}

// ---------------- blocked Cholesky: diagonal block + inv(L11) ----------------
// One block of 64 threads. Factorizes 64x64 block in shared (lower), writes
// dU[k] = 1/l_kk^2, and writes Linv = inv(L11) row-major to g_linv.
__global__ void chol_diag_k(float* __restrict__ G, float* __restrict__ linv,
                            float* __restrict__ dU, int k0) {
    __shared__ float s[NB][NB + 1];
    __shared__ float xs[NB][NB + 1];
    int tid = threadIdx.x;  // 0..63

    for (int j = 0; j < NB; j++)
        s[tid][j] = G[(size_t)(k0 + tid) * AD + k0 + j];
    __syncthreads();

    for (int j = 0; j < NB; j++) {
        float ajj = s[j][j];
        __syncthreads();  // everyone read ajj before thread j overwrites it
        float d = sqrtf(ajj);
        if (tid == j) {
            s[j][j] = d;
            dU[k0 + j] = 1.0f / (d * d);
        }
        if (tid > j) s[tid][j] /= d;
        __syncthreads();
        if (tid > j) {
            float lj = s[tid][j];
            for (int p = j + 1; p <= tid; p++) s[tid][p] -= lj * s[p][j];
        }
        __syncthreads();
    }

    // inv(L11): thread = column c, forward substitution
    int c = tid;
    for (int r = 0; r < c; r++) xs[r][c] = 0.0f;
    xs[c][c] = 1.0f / s[c][c];
    for (int r = c + 1; r < NB; r++) {
        float acc = 0.0f;
        for (int p = c; p < r; p++) acc += s[r][p] * xs[p][c];
        xs[r][c] = -acc / s[r][r];
    }
    // linv[j*NB + p] = Linv[j][p]
    for (int j = 0; j < NB; j++) linv[j * NB + c] = xs[j][c];
}

// ---------------- panel: L21 = A21 * Linv^T, in place in G ----------------
// Each block: 32 rows. Loads its rows + Linv into shared first -> safe in-place.
__global__ void panel_k(float* __restrict__ G, const float* __restrict__ linv, int k0) {
    __shared__ float li[NB][NB + 1];
    __shared__ float ar[32][NB];
    int tid = threadIdx.x;  // 256
    for (int i = tid; i < NB * NB; i += 256) li[i >> 6][i & 63] = linv[i];
    int row0 = k0 + NB + blockIdx.x * 32;
    for (int i = tid; i < 32 * NB; i += 256) {
        int r = i >> 6, p = i & 63;
        ar[r][p] = G[(size_t)(row0 + r) * AD + k0 + p];
    }
    __syncthreads();
    int j = tid & 63;
    int rb = tid >> 6;  // 0..3
    for (int r = rb; r < 32; r += 4) {
        float acc = 0.0f;
#pragma unroll
        for (int p = 0; p < NB; p++) acc += ar[r][p] * li[j][p];
        G[(size_t)(row0 + r) * AD + k0 + j] = acc;
    }
}

// ---------------- generic tiled GEMM with fused epilogues ----------------
// TA: 0 -> A is MxK row-major (A[m*lda+k]);  1 -> A is KxM (A[k*lda+m])
// TB: 0 -> B is KxN row-major (B[k*ldb+n]);  1 -> B is NxK (B[n*ldb+k])
enum { EP_STORE = 0, EP_ADD, EP_SUB, EP_XHAT, EP_XHAT_CLIP, EP_ADMM, EP_ADMM_U0 };

template <int TA, int TB, int EPI, bool GUARD>
__global__ __launch_bounds__(256) void gemm_k(
    const float* __restrict__ A, const float* __restrict__ B, float* __restrict__ C,
    int M, int N, int K, int lda, int ldb, int ldc,
    const float* __restrict__ x0, const float* __restrict__ dU,
    float* __restrict__ ubuf, float* __restrict__ wbuf) {
    __shared__ float As[16][128];
    __shared__ float Bs[16][128];
    int tid = threadIdx.x;
    int bm0 = blockIdx.y * 128;
    int bn0 = blockIdx.x * 128;
    int tx = tid & 15, ty = tid >> 4;

    float acc[8][8];
#pragma unroll
    for (int i = 0; i < 8; i++)
#pragma unroll
        for (int j = 0; j < 8; j++) acc[i][j] = 0.0f;

    for (int k0 = 0; k0 < K; k0 += 16) {
        // ---- load A tile ----
        if (TA == 0) {
#pragma unroll
            for (int L = 0; L < 2; L++) {
                int idx = tid + L * 256;
                int r = idx >> 2;
                int fk = (idx & 3) << 2;
                float4 v = make_float4(0.f, 0.f, 0.f, 0.f);
                if (!GUARD || (bm0 + r) < M)
                    v = *(const float4*)(A + (size_t)(bm0 + r) * lda + k0 + fk);
                As[fk + 0][r] = v.x;
                As[fk + 1][r] = v.y;
                As[fk + 2][r] = v.z;
                As[fk + 3][r] = v.w;
            }
        } else {
#pragma unroll
            for (int L = 0; L < 2; L++) {
                int idx = tid + L * 256;
                int k = idx >> 5;
                int fm = (idx & 31) << 2;
                float4 v = make_float4(0.f, 0.f, 0.f, 0.f);
                if (!GUARD || (bm0 + fm) < M)
                    v = *(const float4*)(A + (size_t)(k0 + k) * lda + bm0 + fm);
                *(float4*)&As[k][fm] = v;
            }
        }
        // ---- load B tile ----
        if (TB == 0) {
#pragma unroll
            for (int L = 0; L < 2; L++) {
                int idx = tid + L * 256;
                int k = idx >> 5;
                int fn = (idx & 31) << 2;
                float4 v = make_float4(0.f, 0.f, 0.f, 0.f);
                if (!GUARD || (bn0 + fn) < N)
                    v = *(const float4*)(B + (size_t)(k0 + k) * ldb + bn0 + fn);
                *(float4*)&Bs[k][fn] = v;
            }
        } else {
#pragma unroll
            for (int L = 0; L < 2; L++) {
                int idx = tid + L * 256;
                int r = idx >> 2;
                int fk = (idx & 3) << 2;
                float4 v = make_float4(0.f, 0.f, 0.f, 0.f);
                if (!GUARD || (bn0 + r) < N)
                    v = *(const float4*)(B + (size_t)(bn0 + r) * ldb + k0 + fk);
                Bs[fk + 0][r] = v.x;
                Bs[fk + 1][r] = v.y;
                Bs[fk + 2][r] = v.z;
                Bs[fk + 3][r] = v.w;
            }
        }
        __syncthreads();
#pragma unroll
        for (int k = 0; k < 16; k++) {
            float arf[8], brf[8];
#pragma unroll
            for (int i = 0; i < 8; i++) arf[i] = As[k][ty * 8 + i];
#pragma unroll
            for (int j = 0; j < 8; j++) brf[j] = Bs[k][tx * 8 + j];
#pragma unroll
            for (int i = 0; i < 8; i++)
#pragma unroll
                for (int j = 0; j < 8; j++) acc[i][j] += arf[i] * brf[j];
        }
        __syncthreads();
    }

    // ---- epilogue ----
    float mnv = 0.f, mxv = 0.f;
    if (EPI == EP_XHAT_CLIP) {
        mnv = o2f(g_mm[0]);
        mxv = o2f(g_mm[1]);
    }
#pragma unroll
    for (int i = 0; i < 8; i++) {
        int row = bm0 + ty * 8 + i;
        if (GUARD && row >= M) continue;
#pragma unroll
        for (int j = 0; j < 8; j++) {
            int col = bn0 + tx * 8 + j;
            if (GUARD && col >= N) continue;
            size_t o = (size_t)row * ldc + col;
            float v = acc[i][j];
            if (EPI == EP_STORE) {
                C[o] = v;
            } else if (EPI == EP_ADD) {
                C[o] += v;
            } else if (EPI == EP_SUB) {
                C[o] -= v;
            } else if (EPI == EP_XHAT) {
                C[o] = dU[col] * (x0[(size_t)row * AD + col] + v);
            } else if (EPI == EP_XHAT_CLIP) {
                float xh = dU[col] * (x0[(size_t)row * AD + col] + v);
                C[o] = fminf(fmaxf(xh, mnv), mxv);
            } else {  // EP_ADMM / EP_ADMM_U0
                float uo = (EPI == EP_ADMM_U0) ? 0.0f : ubuf[o];
                float fxu = v + uo;
                float sa = fabsf(fxu) - 0.1f;  // LAMDA / RHO
                float z = sa > 0.0f ? copysignf(sa, fxu) : 0.0f;
                float un = uo + fxu - z;  // u + fxu - z  (reference formula)
                ubuf[o] = un;
                wbuf[o] = z - un;  // w = z_new - u_new
            }
        }
    }
}

// ---------------- launch ----------------
extern "C" void kernel_launch(void* const* d_in, const int* in_sizes, int n_in,
                              void* d_out, int out_size) {
    const float* y = (const float*)d_in[0];    // (B, M)
    const float* x = (const float*)d_in[1];    // (B, A)
    const float* a = (const float*)d_in[2];    // (M, A)
    const float* phi = (const float*)d_in[3];  // (S, A)
    float* out = (float*)d_out;                // (B, A)

    float *G, *linv, *dU, *x0, *xh, *u, *w;
    cudaGetSymbolAddress((void**)&G, g_G);
    cudaGetSymbolAddress((void**)&linv, g_linv);
    cudaGetSymbolAddress((void**)&dU, g_dU);
    cudaGetSymbolAddress((void**)&x0, g_x0);
    cudaGetSymbolAddress((void**)&xh, g_xh);
    cudaGetSymbolAddress((void**)&u, g_u);
    cudaGetSymbolAddress((void**)&w, g_w);

    dim3 blk(256);

    // min/max of x
    mm_init_k<<<1, 1>>>();
    mm_reduce_k<<<256, 256>>>(x, BD * AD);

    // G = a^T a + phi^T phi
    dim3 gAA(AD / 128, AD / 128);
    gemm_k<1, 0, EP_STORE, false><<<gAA, blk>>>(a, a, G, AD, AD, MD, AD, AD, AD,
                                                nullptr, nullptr, nullptr, nullptr);
    gemm_k<1, 0, EP_ADD, false><<<gAA, blk>>>(phi, phi, G, AD, AD, SD, AD, AD, AD,
                                              nullptr, nullptr, nullptr, nullptr);

    // blocked Cholesky -> dU
    for (int kb = 0; kb < AD / NB; kb++) {
        int k0 = kb * NB;
        chol_diag_k<<<1, NB>>>(G, linv, dU, k0);
        int nrem = AD - k0 - NB;
        if (nrem > 0) {
            panel_k<<<nrem / 32, 256>>>(G, linv, k0);
            dim3 gs((nrem + 127) / 128, (nrem + 127) / 128);
            float* Gp = G + (size_t)(k0 + NB) * AD + k0;
            float* Gc = G + (size_t)(k0 + NB) * AD + (k0 + NB);
            gemm_k<0, 1, EP_SUB, true><<<gs, blk>>>(Gp, Gp, Gc, nrem, nrem, NB, AD, AD, AD,
                                                    nullptr, nullptr, nullptr, nullptr);
        }
    }

    // x0 = y @ a
    gemm_k<0, 0, EP_STORE, false><<<gAA, blk>>>(y, a, x0, BD, AD, MD, MD, AD, AD,
                                                nullptr, nullptr, nullptr, nullptr);

    // iter 1: x_hat = dU * x0 (w = 0), then ADMM update with u = 0
    xhat1_k<<<(BD * AD) / 256, 256>>>(x0, dU, xh);
    dim3 g2(SD / 128, BD / 128);
    gemm_k<0, 1, EP_ADMM_U0, false><<<g2, blk>>>(xh, phi, nullptr, BD, SD, AD, AD, AD, SD,
                                                 nullptr, nullptr, u, w);

    // iters 2..9: full updates
    dim3 g1(AD / 128, BD / 128);
    for (int it = 2; it <= 9; it++) {
        gemm_k<0, 0, EP_XHAT, false><<<g1, blk>>>(w, phi, xh, BD, AD, SD, SD, AD, AD,
                                                  x0, dU, nullptr, nullptr);
        gemm_k<0, 1, EP_ADMM, false><<<g2, blk>>>(xh, phi, nullptr, BD, SD, AD, AD, AD, SD,
                                                  nullptr, nullptr, u, w);
    }

    // iter 10: only x_hat needed -> fused clip, write straight to d_out
    gemm_k<0, 0, EP_XHAT_CLIP, false><<<g1, blk>>>(w, phi, out, BD, AD, SD, SD, AD, AD,
                                                   x0, dU, nullptr, nullptr);
}